// round 5
// baseline (speedup 1.0000x reference)
#include <cuda_runtime.h>
#include <math.h>

// Problem constants
#define TT 1000
#define BB 32
#define NN 2048
#define NN4 512                  // uint4 columns per batch
#define BN4 (BB * NN4)           // 16384 uint4 per timestep
#define TSEG 500                 // timesteps per segment (2 segments)
#define UU 10                    // uint4 loads per prefetch group (500 = 50*10)
// Output layout (concatenated tuple, all f32):
#define OFF_FR 0
#define OFF_CV 65536
#define OFF_SY 131072
#define OFF_TS 131104
#define OFF_AN 196640

// Scratch (fully overwritten every launch; no init needed)
__device__ float g_pop_part[256 * TSEG];    // [(b*2+seg)*4+chunk][tl]
__device__ int4  g_isi[2 * BB * NN];        // [seg][b][n] = {first,last,total,sumg2}

// ---------------------------------------------------------------------------
// Kernel 1: stream input once. grid = 32b x 2seg x 4chunk = 256 blocks x 128.
// Each thread owns one uint4 column (4 neurons) for TSEG timesteps.
// ---------------------------------------------------------------------------
__device__ __forceinline__ void proc_group(
    const uint4* x, int tl0, int tbase, int lane, int w,
    int* last, int* first, int* total, int* sumg2, int (*pop_s)[TSEG])
{
    #pragma unroll
    for (int j = 0; j < UU; j++) {
        const int tl = tl0 + j;
        const int t  = tbase + tl;
        uint4 u = x[j];
        int s0 = (int)(u.x >> 29);   // 1.0f -> 1, 0.0f -> 0
        int s1 = (int)(u.y >> 29);
        int s2 = (int)(u.z >> 29);
        int s3 = (int)(u.w >> 29);
        int c  = (s0 + s1) + (s2 + s3);
        unsigned psum = __reduce_add_sync(0xffffffffu, (unsigned)c);
        if (lane == 0) pop_s[w][tl] = (int)psum;

        int sv[4] = {s0, s1, s2, s3};
        #pragma unroll
        for (int k = 0; k < 4; k++) {
            if (sv[k]) {
                if (last[k] >= 0) {
                    int g = t - last[k];
                    sumg2[k] += g * g;
                } else {
                    first[k] = t;
                }
                last[k] = t;
                total[k]++;
            }
        }
    }
}

__global__ __launch_bounds__(128, 2)
void spike_main(const float* __restrict__ in) {
    const int bid   = blockIdx.x;          // 0..255
    const int b     = bid >> 3;            // batch
    const int seg   = (bid >> 2) & 1;      // time segment
    const int chunk = bid & 3;             // neuron chunk (512 neurons)
    const int tid   = threadIdx.x;         // 0..127
    const int w     = tid >> 5;
    const int lane  = tid & 31;
    const int tbase = seg * TSEG;
    const int c4    = (chunk << 7) | tid;  // uint4 column 0..511

    __shared__ int pop_s[4][TSEG];         // 8 KB

    const uint4* p = (const uint4*)in + (size_t)tbase * BN4 + (size_t)b * NN4 + c4;

    int last[4]  = {-1, -1, -1, -1};
    int first[4] = {-1, -1, -1, -1};
    int total[4] = {0, 0, 0, 0};
    int sumg2[4] = {0, 0, 0, 0};

    uint4 A[UU], Bf[UU];

    // Prime: group 0 -> A
    #pragma unroll
    for (int i = 0; i < UU; i++) A[i] = p[(size_t)i * BN4];

    // 50 groups, ping-pong in pairs (25 iterations)
    #pragma unroll 1
    for (int gp = 0; gp < 25; gp++) {
        const int tA = gp * 2 * UU;            // group 2*gp   (in A)
        const int tB = tA + UU;                // group 2*gp+1 (to Bf)
        // load odd group while processing A
        #pragma unroll
        for (int i = 0; i < UU; i++) Bf[i] = p[(size_t)(tB + i) * BN4];
        proc_group(A, tA, tbase, lane, w, last, first, total, sumg2, pop_s);
        // load next even group while processing Bf
        if (gp < 24) {
            const int tA2 = tB + UU;
            #pragma unroll
            for (int i = 0; i < UU; i++) A[i] = p[(size_t)(tA2 + i) * BN4];
        }
        proc_group(Bf, tB, tbase, lane, w, last, first, total, sumg2, pop_s);
    }

    // Per-neuron segment stats -> scratch (4 consecutive int4 per thread)
    const int nbase = (seg * BB + b) * NN + (chunk << 9) + (tid << 2);
    #pragma unroll
    for (int k = 0; k < 4; k++)
        g_isi[nbase + k] = make_int4(first[k], last[k], total[k], sumg2[k]);

    __syncthreads();
    // Reduce 4 warp rows -> per-block population partial
    const int row = ((b * 2 + seg) * 4 + chunk);
    #pragma unroll
    for (int r = 0; r < 4; r++) {
        int tl = tid + r * 128;
        if (tl < TSEG) {
            int s = pop_s[0][tl] + pop_s[1][tl] + pop_s[2][tl] + pop_s[3][tl];
            g_pop_part[row * TSEG + tl] = (float)s;
        }
    }
}

// ---------------------------------------------------------------------------
// Kernel 2: per-batch finish. grid = 32 blocks x 256 threads.
// Merges 2 ISI segments per neuron (2048 per block), emits per-neuron outputs,
// active counts, and the population lag-1 circular autocorrelation.
// ---------------------------------------------------------------------------
__global__ __launch_bounds__(256)
void spike_finish(float* __restrict__ out) {
    const int b    = blockIdx.x;    // 0..31
    const int tid  = threadIdx.x;
    const int w    = tid >> 5;
    const int lane = tid & 31;

    __shared__ float  pop[TT];
    __shared__ int    act_s[8];
    __shared__ double red1[8], red2[8], redc[8];

    // ---- per-neuron merge + outputs ----
    int act = 0;
    #pragma unroll 1
    for (int r = 0; r < 8; r++) {
        const int n = r * 256 + tid;
        int4 v0 = g_isi[(0 * BB + b) * NN + n];
        int4 v1 = g_isi[(1 * BB + b) * NN + n];

        int first = -1, last = -1, total = 0, sumg2 = 0;
        if (v0.z > 0) { first = v0.x; last = v0.y; total = v0.z; sumg2 = v0.w; }
        if (v1.z > 0) {
            if (total > 0) {
                int g = v1.x - last;
                sumg2 += g * g;
            } else {
                first = v1.x;
            }
            last   = v1.y;
            total += v1.z;
            sumg2 += v1.w;
        }

        const int idx = b * NN + n;
        float tot = (float)total;
        out[OFF_FR + idx] = tot / (TT * 0.001f);
        out[OFF_TS + idx] = tot;

        float cv = 0.0f;
        int cnt = total - 1;
        if (cnt >= 1) {
            float fc   = (float)cnt;
            float mean = (float)(last - first) / fc;
            float var  = ((float)sumg2 - fc * mean * mean) / fmaxf(fc - 1.0f, 1.0f);
            cv = sqrtf(fmaxf(var, 0.0f)) / fmaxf(mean, 1e-12f);
        }
        out[OFF_CV + idx] = cv;

        act += (total > 0);
    }
    // block-sum active count
    act = (int)__reduce_add_sync(0xffffffffu, (unsigned)act);
    if (lane == 0) act_s[w] = act;

    // ---- assemble pop[t] ----
    #pragma unroll
    for (int r = 0; r < 4; r++) {
        int t = tid + r * 256;
        if (t < TT) {
            int sg = t / TSEG;
            int tl = t - sg * TSEG;
            int rowb = (b * 2 + sg) * 4;
            float s = g_pop_part[(rowb + 0) * TSEG + tl]
                    + g_pop_part[(rowb + 1) * TSEG + tl]
                    + g_pop_part[(rowb + 2) * TSEG + tl]
                    + g_pop_part[(rowb + 3) * TSEG + tl];
            pop[t] = s;
        }
    }
    __syncthreads();

    // ---- circular lag-1 autocorr: num = Sc - S1^2/T, den = S2 - S1^2/T ----
    double s1 = 0.0, s2 = 0.0, sc = 0.0;
    #pragma unroll
    for (int r = 0; r < 4; r++) {
        int t = tid + r * 256;
        if (t < TT) {
            double x  = (double)pop[t];
            int tp = (t == 0) ? (TT - 1) : (t - 1);
            double xp = (double)pop[tp];
            s1 += x;
            s2 += x * x;
            sc += x * xp;
        }
    }
    #pragma unroll
    for (int o = 16; o > 0; o >>= 1) {
        s1 += __shfl_down_sync(0xffffffffu, s1, o);
        s2 += __shfl_down_sync(0xffffffffu, s2, o);
        sc += __shfl_down_sync(0xffffffffu, sc, o);
    }
    if (lane == 0) { red1[w] = s1; red2[w] = s2; redc[w] = sc; }
    __syncthreads();
    if (tid == 0) {
        double S1 = 0.0, S2 = 0.0, Sc = 0.0;
        int a = 0;
        #pragma unroll
        for (int k = 0; k < 8; k++) {
            S1 += red1[k]; S2 += red2[k]; Sc += redc[k]; a += act_s[k];
        }
        double mt  = S1 * S1 / (double)TT;
        double num = Sc - mt;
        double den = S2 - mt;
        out[OFF_SY + b] = (den > 0.0) ? (float)(num / fmax(den, 1e-12)) : 0.0f;
        out[OFF_AN + b] = (float)a;
    }
}

extern "C" void kernel_launch(void* const* d_in, const int* in_sizes, int n_in,
                              void* d_out, int out_size) {
    const float* in = (const float*)d_in[0];
    float* out = (float*)d_out;
    spike_main<<<256, 128>>>(in);
    spike_finish<<<BB, 256>>>(out);
}

// round 6
// speedup vs baseline: 2.6640x; 2.6640x over previous
#include <cuda_runtime.h>
#include <math.h>

// Problem constants
#define TT 1000
#define BB 32
#define NN 2048
#define NC2 1024                 // uint2 (2-neuron) columns per batch
#define BN2 (BB * NC2)           // 32768 uint2 per timestep
#define TSEG 500                 // timesteps per segment (2 segments)
#define UU 10                    // uint2 loads per prefetch group (500 = 50*10)
// Output layout (concatenated tuple, all f32):
#define OFF_FR 0
#define OFF_CV 65536
#define OFF_SY 131072
#define OFF_TS 131104
#define OFF_AN 196640

// Scratch (fully overwritten every launch; no init needed)
__device__ float g_pop_part[512 * TSEG];    // [(b*2+seg)*8+chunk][tl]
__device__ int4  g_isi[2 * BB * NN];        // [seg][b][n] = {first,last,total,sumg2}
__device__ float g_active_part[256];        // per (b,chunk-of-256-neurons)

// ---------------------------------------------------------------------------
// Kernel 1: stream input once. grid = 32b x 2seg x 8chunk = 512 blocks x 128.
// Each thread owns one uint2 column (2 neurons) for TSEG timesteps.
// ---------------------------------------------------------------------------
__device__ __forceinline__ void proc_group(
    const uint2* x, int tl0, int tbase, int lane, int w,
    int* last, int* first, int* total, int* sumg2, int (*pop_s)[TSEG])
{
    #pragma unroll
    for (int j = 0; j < UU; j++) {
        const int tl = tl0 + j;
        const int t  = tbase + tl;
        uint2 u = x[j];
        int s0 = (int)(u.x >> 29);   // 1.0f -> 1, 0.0f -> 0
        int s1 = (int)(u.y >> 29);
        unsigned psum = __reduce_add_sync(0xffffffffu, (unsigned)(s0 + s1));
        if (lane == 0) pop_s[w][tl] = (int)psum;

        if (s0) {
            if (last[0] >= 0) { int g = t - last[0]; sumg2[0] += g * g; }
            else              { first[0] = t; }
            last[0] = t; total[0]++;
        }
        if (s1) {
            if (last[1] >= 0) { int g = t - last[1]; sumg2[1] += g * g; }
            else              { first[1] = t; }
            last[1] = t; total[1]++;
        }
    }
}

__global__ __launch_bounds__(128, 4)
void spike_main(const float* __restrict__ in) {
    const int bid   = blockIdx.x;          // 0..511
    const int b     = bid >> 4;            // batch
    const int seg   = (bid >> 3) & 1;      // time segment
    const int chunk = bid & 7;             // 128 uint2 columns each
    const int tid   = threadIdx.x;         // 0..127
    const int w     = tid >> 5;
    const int lane  = tid & 31;
    const int tbase = seg * TSEG;
    const int col   = (chunk << 7) | tid;  // uint2 column 0..1023

    __shared__ int pop_s[4][TSEG];         // 8 KB

    const uint2* p = (const uint2*)in + (size_t)tbase * BN2 + (size_t)b * NC2 + col;

    int last[2]  = {-1, -1};
    int first[2] = {-1, -1};
    int total[2] = {0, 0};
    int sumg2[2] = {0, 0};

    uint2 A[UU], Bf[UU];

    // Prime: group 0 -> A
    #pragma unroll
    for (int i = 0; i < UU; i++) A[i] = p[(size_t)i * BN2];

    // 50 groups, ping-pong in pairs (25 iterations), no register copies
    #pragma unroll 1
    for (int gp = 0; gp < 25; gp++) {
        const int tA = gp * 2 * UU;
        const int tB = tA + UU;
        #pragma unroll
        for (int i = 0; i < UU; i++) Bf[i] = p[(size_t)(tB + i) * BN2];
        proc_group(A, tA, tbase, lane, w, last, first, total, sumg2, pop_s);
        if (gp < 24) {
            const int tA2 = tB + UU;
            #pragma unroll
            for (int i = 0; i < UU; i++) A[i] = p[(size_t)(tA2 + i) * BN2];
        }
        proc_group(Bf, tB, tbase, lane, w, last, first, total, sumg2, pop_s);
    }

    // Per-neuron segment stats -> scratch (2 consecutive int4 per thread)
    const int nbase = (seg * BB + b) * NN + (col << 1);
    g_isi[nbase + 0] = make_int4(first[0], last[0], total[0], sumg2[0]);
    g_isi[nbase + 1] = make_int4(first[1], last[1], total[1], sumg2[1]);

    __syncthreads();
    // Reduce 4 warp rows -> per-block population partial
    #pragma unroll
    for (int r = 0; r < 4; r++) {
        int tl = tid + r * 128;
        if (tl < TSEG) {
            int s = pop_s[0][tl] + pop_s[1][tl] + pop_s[2][tl] + pop_s[3][tl];
            g_pop_part[bid * TSEG + tl] = (float)s;
        }
    }
}

// ---------------------------------------------------------------------------
// Kernel 2: merge 2 time segments per neuron. grid = 256 blocks x 256.
// ---------------------------------------------------------------------------
__global__ __launch_bounds__(256)
void spike_merge(float* __restrict__ out) {
    const int bid   = blockIdx.x;          // 0..255
    const int b     = bid >> 3;
    const int chunk = bid & 7;             // 256 neurons
    const int tid   = threadIdx.x;
    const int n     = (chunk << 8) | tid;
    const int w     = tid >> 5;
    const int lane  = tid & 31;

    __shared__ int active_s[8];

    int4 v0 = g_isi[(0 * BB + b) * NN + n];
    int4 v1 = g_isi[(1 * BB + b) * NN + n];

    int first = -1, last = -1, total = 0, sumg2 = 0;
    if (v0.z > 0) { first = v0.x; last = v0.y; total = v0.z; sumg2 = v0.w; }
    if (v1.z > 0) {
        if (total > 0) { int g = v1.x - last; sumg2 += g * g; }
        else           { first = v1.x; }
        last   = v1.y;
        total += v1.z;
        sumg2 += v1.w;
    }

    const int idx = b * NN + n;
    float tot = (float)total;
    out[OFF_FR + idx] = tot / (TT * 0.001f);
    out[OFF_TS + idx] = tot;

    float cv = 0.0f;
    int cnt = total - 1;
    if (cnt >= 1) {
        float fc   = (float)cnt;
        float mean = (float)(last - first) / fc;
        float var  = ((float)sumg2 - fc * mean * mean) / fmaxf(fc - 1.0f, 1.0f);
        cv = sqrtf(fmaxf(var, 0.0f)) / fmaxf(mean, 1e-12f);
    }
    out[OFF_CV + idx] = cv;

    unsigned am = __ballot_sync(0xffffffffu, total > 0);
    if (lane == 0) active_s[w] = __popc(am);
    __syncthreads();
    if (tid == 0) {
        int a = 0;
        #pragma unroll
        for (int k = 0; k < 8; k++) a += active_s[k];
        g_active_part[bid] = (float)a;
    }
}

// ---------------------------------------------------------------------------
// Kernel 3: per-batch population autocorrelation + active count. grid = 32.
// ---------------------------------------------------------------------------
__global__ __launch_bounds__(256)
void spike_sync(float* __restrict__ out) {
    const int b    = blockIdx.x;    // 0..31
    const int tid  = threadIdx.x;
    const int w    = tid >> 5;
    const int lane = tid & 31;

    __shared__ float  pop[TT];
    __shared__ double red1[8], red2[8], redc[8];

    // Assemble pop[t]: sum the 8 chunk partials of the right (seg,tl)
    #pragma unroll
    for (int r = 0; r < 4; r++) {
        int t = tid + r * 256;
        if (t < TT) {
            int sg = (t >= TSEG) ? 1 : 0;
            int tl = t - sg * TSEG;
            int rowb = (b << 4) | (sg << 3);         // ((b*2+sg)*8)
            float s = 0.0f;
            #pragma unroll
            for (int k = 0; k < 8; k++)
                s += g_pop_part[(rowb + k) * TSEG + tl];
            pop[t] = s;
        }
    }
    __syncthreads();

    // circular lag-1 autocorr: num = Sc - S1^2/T, den = S2 - S1^2/T
    double s1 = 0.0, s2 = 0.0, sc = 0.0;
    #pragma unroll
    for (int r = 0; r < 4; r++) {
        int t = tid + r * 256;
        if (t < TT) {
            double x  = (double)pop[t];
            int tp = (t == 0) ? (TT - 1) : (t - 1);
            double xp = (double)pop[tp];
            s1 += x;
            s2 += x * x;
            sc += x * xp;
        }
    }
    #pragma unroll
    for (int o = 16; o > 0; o >>= 1) {
        s1 += __shfl_down_sync(0xffffffffu, s1, o);
        s2 += __shfl_down_sync(0xffffffffu, s2, o);
        sc += __shfl_down_sync(0xffffffffu, sc, o);
    }
    if (lane == 0) { red1[w] = s1; red2[w] = s2; redc[w] = sc; }
    __syncthreads();
    if (tid == 0) {
        double S1 = 0.0, S2 = 0.0, Sc = 0.0;
        #pragma unroll
        for (int k = 0; k < 8; k++) { S1 += red1[k]; S2 += red2[k]; Sc += redc[k]; }
        double mt  = S1 * S1 / (double)TT;
        double num = Sc - mt;
        double den = S2 - mt;
        out[OFF_SY + b] = (den > 0.0) ? (float)(num / fmax(den, 1e-12)) : 0.0f;
        float a = 0.0f;
        #pragma unroll
        for (int k = 0; k < 8; k++) a += g_active_part[b * 8 + k];
        out[OFF_AN + b] = a;
    }
}

extern "C" void kernel_launch(void* const* d_in, const int* in_sizes, int n_in,
                              void* d_out, int out_size) {
    const float* in = (const float*)d_in[0];
    float* out = (float*)d_out;
    spike_main<<<512, 128>>>(in);
    spike_merge<<<256, 256>>>(out);
    spike_sync<<<BB, 256>>>(out);
}